// round 13
// baseline (speedup 1.0000x reference)
#include <cuda_runtime.h>
#include <cuda_bf16.h>
#include <cstdint>

// GRU B=4096, T=512, I=H=32 — single fused kernel.
// Per warp (2 batch rows): produce gx for the next 8-step chunk via mma.sync
// bf16 3-term hi/lo split (tensor pipe, fp32 accum) into per-warp smem, then run
// the fp32 SIMT recurrence (fma pipe) on it. No gx DRAM traffic, no kernel A.

#define GRU_T 512
#define GRU_B 4096
#define WPB 4
#define CHUNK 8
#define NCH (GRU_T / CHUNK)     // 64
#define FULL 0xffffffffu

typedef unsigned long long u64;

// ── dynamic smem layout (bytes) ──
#define S_WHI   0               // W_ih hi bf16: 96 rows × 80B
#define S_WLO   7680            // W_ih lo
#define S_BIAS  15360           // 96 × f32
#define S_XS    15744           // x fp32 staging: 4 warps × 2 buf × 2048B
#define S_XT    32128           // x bf16 tiles: 4 warps × (hi 1280 + lo 1280)
#define S_GX    42368           // gx: 4 warps × 1536 f32 (6144B)
#define S_TOTAL 66944

// ── helpers ──
__device__ __forceinline__ u64 ffma2(u64 a, u64 b, u64 c) {
    u64 d;
    asm("fma.rn.f32x2 %0, %1, %2, %3;" : "=l"(d) : "l"(a), "l"(b), "l"(c));
    return d;
}
__device__ __forceinline__ u64 pack2(float lo, float hi) {
    u64 r;
    asm("mov.b64 %0, {%1, %2};" : "=l"(r) : "f"(lo), "f"(hi));
    return r;
}
__device__ __forceinline__ float2 unpack2(u64 v) {
    float2 f;
    asm("mov.b64 {%0, %1}, %2;" : "=f"(f.x), "=f"(f.y) : "l"(v));
    return f;
}
__device__ __forceinline__ float sigmoid_fast(float v) {
    float e = __expf(-v);
    return __fdividef(1.0f, 1.0f + e);
}
__device__ __forceinline__ float tanh_fast(float v) {
    float a = fabsf(v);
    float e = __expf(-2.0f * a);
    float t = __fdividef(1.0f - e, 1.0f + e);
    return copysignf(t, v);
}
__device__ __forceinline__ void cpasync16(uint32_t dst, const float* src) {
    size_t s = __cvta_generic_to_global(src);
    asm volatile("cp.async.cg.shared.global [%0], [%1], 16;" :: "r"(dst), "l"(s) : "memory");
}
__device__ __forceinline__ uint32_t smem_u32(const void* p) {
    uint32_t a;
    asm("{ .reg .u64 t; cvta.to.shared.u64 t, %1; cvt.u32.u64 %0, t; }" : "=r"(a) : "l"(p));
    return a;
}
__device__ __forceinline__ void ldsm_x4(uint32_t a[4], uint32_t addr) {
    asm volatile("ldmatrix.sync.aligned.m8n8.x4.shared.b16 {%0,%1,%2,%3}, [%4];"
                 : "=r"(a[0]), "=r"(a[1]), "=r"(a[2]), "=r"(a[3]) : "r"(addr));
}
__device__ __forceinline__ void ldsm_x2(uint32_t b[2], uint32_t addr) {
    asm volatile("ldmatrix.sync.aligned.m8n8.x2.shared.b16 {%0,%1}, [%2];"
                 : "=r"(b[0]), "=r"(b[1]) : "r"(addr));
}
__device__ __forceinline__ void mma16816(float c[4], const uint32_t a[4], const uint32_t b[2]) {
    asm volatile(
        "mma.sync.aligned.m16n8k16.row.col.f32.bf16.bf16.f32 "
        "{%0,%1,%2,%3}, {%4,%5,%6,%7}, {%8,%9}, {%0,%1,%2,%3};"
        : "+f"(c[0]), "+f"(c[1]), "+f"(c[2]), "+f"(c[3])
        : "r"(a[0]), "r"(a[1]), "r"(a[2]), "r"(a[3]), "r"(b[0]), "r"(b[1]));
}

__global__ void __launch_bounds__(128, 3) gru_fused_kernel(
        const float* __restrict__ x,
        const float* __restrict__ W_ih,
        const float* __restrict__ W_hh,
        const float* __restrict__ b_ih,
        const float* __restrict__ b_hh,
        const float* __restrict__ w_head,
        const float* __restrict__ b_head,
        float* __restrict__ out) {
    extern __shared__ __align__(128) char sm[];
    __shared__ __align__(16) float hbuf[WPB][2][2][32];  // [warp][buf][row][j]

    const int tid = threadIdx.x;
    const int w = tid >> 5;
    const int lane = tid & 31;
    const int g = blockIdx.x * WPB + w;      // warp owns batch rows 2g, 2g+1

    // ── CTA init: W_ih → smem bf16 hi/lo (80B row stride), bias ──
    for (int i = tid; i < 96 * 32; i += 128) {
        int r = i >> 5, c = i & 31;
        float v = W_ih[i];
        __nv_bfloat16 hi = __float2bfloat16(v);
        __nv_bfloat16 lo = __float2bfloat16(v - __bfloat162float(hi));
        *(__nv_bfloat16*)(sm + S_WHI + r * 80 + c * 2) = hi;
        *(__nv_bfloat16*)(sm + S_WLO + r * 80 + c * 2) = lo;
    }
    if (tid < 96)
        *(float*)(sm + S_BIAS + tid * 4) = b_ih[tid] + (tid < 64 ? b_hh[tid] : 0.0f);

    // ── W_hh rows j, 32+j, 64+j packed into registers (consumer workhorse) ──
    u64 whr[16], whz[16], whn[16];
    {
        const u64* a = (const u64*)(W_hh + (size_t)lane * 32);
        const u64* c = (const u64*)(W_hh + (size_t)(32 + lane) * 32);
        const u64* d = (const u64*)(W_hh + (size_t)(64 + lane) * 32);
#pragma unroll
        for (int k = 0; k < 16; k++) { whr[k] = a[k]; whz[k] = c[k]; whn[k] = d[k]; }
    }
    const u64 anh0 = pack2(b_hh[64 + lane], 0.0f);
    const u64 zero2 = pack2(0.0f, 0.0f);
    __syncthreads();

    // ── per-warp smem addresses ──
    const uint32_t smb = smem_u32(sm);
    const uint32_t xsb  = smb + S_XS + w * 4096;            // fp32 x staging (2 bufs)
    const uint32_t xth  = smb + S_XT + w * 2560;            // bf16 x hi tile
    const uint32_t xtl  = xth + 1280;                       // bf16 x lo tile
    float* gxs = (float*)(sm + S_GX + w * 6144);            // gx chunk (16 rows × 96)
    const float* biasf = (const float*)(sm + S_BIAS);

    const float* xr0 = x + (size_t)(2 * g) * GRU_T * 32;
    const float* xr1 = x + (size_t)(2 * g + 1) * GRU_T * 32;

    // frag addressing constants
    const int gq = lane >> 3;
    const uint32_t a_roff = (uint32_t)(((gq & 1) * 8 + (lane & 7)) * 80 + (gq >> 1) * 16);
    const uint32_t sts_off = (uint32_t)((lane >> 1) * 80 + (lane & 1) * 32);
    const int mh = lane & 15;
    const uint32_t w_roff = (uint32_t)((mh & 7) * 80 + ((mh >> 3) & 1) * 16);

    // ── x staging: 2KB per chunk per warp (r0 8 steps = 1KB, r1 = 1KB) ──
    auto stage_x = [&](int cc) {
        uint32_t dst = xsb + (cc & 1) * 2048;
        const float* s0 = xr0 + (size_t)cc * CHUNK * 32;
        const float* s1 = xr1 + (size_t)cc * CHUNK * 32;
        cpasync16(dst + lane * 16, s0 + lane * 4);
        cpasync16(dst + 512 + lane * 16, s0 + 128 + lane * 4);
        cpasync16(dst + 1024 + lane * 16, s1 + lane * 4);
        cpasync16(dst + 1536 + lane * 16, s1 + 128 + lane * 4);
    };
    stage_x(0);
    asm volatile("cp.async.commit_group;" ::: "memory");
    stage_x(1);
    asm volatile("cp.async.commit_group;" ::: "memory");

    hbuf[w][0][0][lane] = 0.0f;
    hbuf[w][0][1][lane] = 0.0f;
    float h0 = 0.0f, h1 = 0.0f;
    __syncwarp();

#pragma unroll 1
    for (int c = 0; c < NCH; c++) {
        // ── produce gx chunk c (tensor pipe) ──
        asm volatile("cp.async.wait_group 1;" ::: "memory");
        __syncwarp();

        // fp32 x → hi/lo bf16 tiles. Lane covers tile row lane/2, half lane&1.
        {
            const float4* xp = (const float4*)(sm + (xsb - smb) + (c & 1) * 2048
                                               + (lane >> 1) * 128 + (lane & 1) * 64);
            uint32_t hu[8], lu[8];
#pragma unroll
            for (int q = 0; q < 4; q++) {
                float4 v = xp[q];
                __nv_bfloat162 hA = __floats2bfloat162_rn(v.x, v.y);
                __nv_bfloat162 hB = __floats2bfloat162_rn(v.z, v.w);
                __nv_bfloat162 lA = __floats2bfloat162_rn(v.x - __bfloat162float(hA.x),
                                                          v.y - __bfloat162float(hA.y));
                __nv_bfloat162 lB = __floats2bfloat162_rn(v.z - __bfloat162float(hB.x),
                                                          v.w - __bfloat162float(hB.y));
                hu[2 * q]     = *(uint32_t*)&hA;
                hu[2 * q + 1] = *(uint32_t*)&hB;
                lu[2 * q]     = *(uint32_t*)&lA;
                lu[2 * q + 1] = *(uint32_t*)&lB;
            }
            uint4* dh = (uint4*)(sm + (xth - smb) + sts_off);
            uint4* dl = (uint4*)(sm + (xtl - smb) + sts_off);
            dh[0] = make_uint4(hu[0], hu[1], hu[2], hu[3]);
            dh[1] = make_uint4(hu[4], hu[5], hu[6], hu[7]);
            dl[0] = make_uint4(lu[0], lu[1], lu[2], lu[3]);
            dl[1] = make_uint4(lu[4], lu[5], lu[6], lu[7]);
        }
        __syncwarp();

        uint32_t ah[2][4], al[2][4];
#pragma unroll
        for (int ks = 0; ks < 2; ks++) {
            ldsm_x4(ah[ks], xth + a_roff + ks * 32);
            ldsm_x4(al[ks], xtl + a_roff + ks * 32);
        }

        // prefetch x for chunk c+2 (overwrites buf c&1 — reads done, syncwarp'd)
        if (c + 2 < NCH) stage_x(c + 2);
        asm volatile("cp.async.commit_group;" ::: "memory");

        // 12 n-tiles × (3-term split × 2 ksteps); C init = bias; STS to gxs.
#pragma unroll
        for (int nt = 0; nt < 12; nt++) {
            uint32_t bh0[2], bh1[2], bl0[2], bl1[2];
            ldsm_x2(bh0, smb + S_WHI + nt * 640 + w_roff);
            ldsm_x2(bh1, smb + S_WHI + nt * 640 + w_roff + 32);
            ldsm_x2(bl0, smb + S_WLO + nt * 640 + w_roff);
            ldsm_x2(bl1, smb + S_WLO + nt * 640 + w_roff + 32);
            float2 b2 = *(const float2*)(biasf + nt * 8 + (lane & 3) * 2);
            float cc[4] = { b2.x, b2.y, b2.x, b2.y };
            mma16816(cc, ah[0], bh0);
            mma16816(cc, ah[1], bh1);
            mma16816(cc, ah[0], bl0);
            mma16816(cc, ah[1], bl1);
            mma16816(cc, al[0], bh0);
            mma16816(cc, al[1], bh1);
            float* o = gxs + (lane >> 2) * 96 + nt * 8 + (lane & 3) * 2;
            *(float2*)o         = make_float2(cc[0], cc[1]);
            *(float2*)(o + 768) = make_float2(cc[2], cc[3]);
        }
        __syncwarp();

        // ── consume: 8 recurrence steps (fma pipe) ──
#pragma unroll
        for (int tl = 0; tl < CHUNK; tl++) {
            const int t = c * CHUNK + tl;
            const ulonglong2* hq0 = (const ulonglong2*)&hbuf[w][t & 1][0][0];
            const ulonglong2* hq1 = (const ulonglong2*)&hbuf[w][t & 1][1][0];

            u64 ar0 = zero2, az0 = zero2, an0 = anh0;
            u64 ar1 = zero2, az1 = zero2, an1 = anh0;
#pragma unroll
            for (int q = 0; q < 8; q++) {
                ulonglong2 ha = hq0[q];
                ulonglong2 hb = hq1[q];
                ar0 = ffma2(ha.x, whr[2 * q], ar0);
                az0 = ffma2(ha.x, whz[2 * q], az0);
                an0 = ffma2(ha.x, whn[2 * q], an0);
                ar1 = ffma2(hb.x, whr[2 * q], ar1);
                az1 = ffma2(hb.x, whz[2 * q], az1);
                an1 = ffma2(hb.x, whn[2 * q], an1);
                ar0 = ffma2(ha.y, whr[2 * q + 1], ar0);
                az0 = ffma2(ha.y, whz[2 * q + 1], az0);
                an0 = ffma2(ha.y, whn[2 * q + 1], an0);
                ar1 = ffma2(hb.y, whr[2 * q + 1], ar1);
                az1 = ffma2(hb.y, whz[2 * q + 1], az1);
                an1 = ffma2(hb.y, whn[2 * q + 1], an1);
            }
            float gxr0 = gxs[tl * 96 + lane];
            float gxz0 = gxs[tl * 96 + 32 + lane];
            float gxn0 = gxs[tl * 96 + 64 + lane];
            float gxr1 = gxs[768 + tl * 96 + lane];
            float gxz1 = gxs[768 + tl * 96 + 32 + lane];
            float gxn1 = gxs[768 + tl * 96 + 64 + lane];

            float2 fr0 = unpack2(ar0), fz0 = unpack2(az0), fn0 = unpack2(an0);
            float2 fr1 = unpack2(ar1), fz1 = unpack2(az1), fn1 = unpack2(an1);
            float r0 = sigmoid_fast(gxr0 + fr0.x + fr0.y);
            float r1 = sigmoid_fast(gxr1 + fr1.x + fr1.y);
            float z0 = sigmoid_fast(gxz0 + fz0.x + fz0.y);
            float z1 = sigmoid_fast(gxz1 + fz1.x + fz1.y);
            float n0 = tanh_fast(fmaf(r0, fn0.x + fn0.y, gxn0));
            float n1 = tanh_fast(fmaf(r1, fn1.x + fn1.y, gxn1));
            h0 = fmaf(z0, h0 - n0, n0);
            h1 = fmaf(z1, h1 - n1, n1);

            hbuf[w][(t + 1) & 1][0][lane] = h0;
            hbuf[w][(t + 1) & 1][1][lane] = h1;
            __syncwarp();
        }
    }

    // ── head ──
    float v0 = h0 * w_head[lane];
    float v1 = h1 * w_head[lane];
#pragma unroll
    for (int off = 16; off > 0; off >>= 1) {
        v0 += __shfl_xor_sync(FULL, v0, off);
        v1 += __shfl_xor_sync(FULL, v1, off);
    }
    if (lane == 0) {
        out[2 * g]     = v0 + b_head[0];
        out[2 * g + 1] = v1 + b_head[0];
    }
}

extern "C" void kernel_launch(void* const* d_in, const int* in_sizes, int n_in,
                              void* d_out, int out_size) {
    const float* x      = (const float*)d_in[0];
    const float* W_ih   = (const float*)d_in[1];
    const float* W_hh   = (const float*)d_in[2];
    const float* b_ih   = (const float*)d_in[3];
    const float* b_hh   = (const float*)d_in[4];
    const float* w_head = (const float*)d_in[5];
    const float* b_head = (const float*)d_in[6];
    float* out = (float*)d_out;

    cudaFuncSetAttribute(gru_fused_kernel,
                         cudaFuncAttributeMaxDynamicSharedMemorySize, S_TOTAL);
    gru_fused_kernel<<<GRU_B / (2 * WPB), 32 * WPB, S_TOTAL>>>(
        x, W_ih, W_hh, b_ih, b_hh, w_head, b_head, out);
}

// round 14
// speedup vs baseline: 1.0216x; 1.0216x over previous
#include <cuda_runtime.h>
#include <cuda_bf16.h>
#include <cstdint>

// GRU B=4096, T=512, I=H=32 — fused single-wave kernel.
// 128 CTAs × 8 warps × 4 batch rows/warp (one wave on 148 SMs, no tail wave).
// Per chunk (8 steps): produce gx via mma.sync bf16 3-term hi/lo split (tensor
// pipe, fp32 accum) into per-warp smem; then run fp32 SIMT recurrence (fma pipe).

#define GRU_T 512
#define GRU_B 4096
#define WPB 8            // warps per CTA
#define RPW 4            // batch rows per warp
#define CHUNK 8
#define NCH (GRU_T / CHUNK)     // 64
#define GRID (GRU_B / (WPB * RPW))  // 128
#define FULL 0xffffffffu

typedef unsigned long long u64;

// ── dynamic smem layout (bytes) ──
#define S_WHI   0                        // W_ih hi bf16: 96 rows × 80B
#define S_WLO   7680                     // W_ih lo
#define S_BIAS  15360                    // 96 × f32
#define S_XS    15744                    // x fp32 staging: 8 warps × 2 buf × 4096B
#define S_XT    81280                    // x bf16 tiles: 8 × (hi 2560 + lo 2560)
#define S_GX    122240                   // gx: 8 warps × 3072 f32 (12288B)
#define S_HB    220544                   // hbuf: 8 warps × 2 buf × 4 rows × 32 f32
#define S_TOTAL 228736

// ── helpers ──
__device__ __forceinline__ u64 ffma2(u64 a, u64 b, u64 c) {
    u64 d;
    asm("fma.rn.f32x2 %0, %1, %2, %3;" : "=l"(d) : "l"(a), "l"(b), "l"(c));
    return d;
}
__device__ __forceinline__ u64 pack2(float lo, float hi) {
    u64 r;
    asm("mov.b64 %0, {%1, %2};" : "=l"(r) : "f"(lo), "f"(hi));
    return r;
}
__device__ __forceinline__ float2 unpack2(u64 v) {
    float2 f;
    asm("mov.b64 {%0, %1}, %2;" : "=f"(f.x), "=f"(f.y) : "l"(v));
    return f;
}
__device__ __forceinline__ float sigmoid_fast(float v) {
    float e = __expf(-v);
    return __fdividef(1.0f, 1.0f + e);
}
__device__ __forceinline__ float tanh_fast(float v) {
    float a = fabsf(v);
    float e = __expf(-2.0f * a);
    float t = __fdividef(1.0f - e, 1.0f + e);
    return copysignf(t, v);
}
__device__ __forceinline__ void cpasync16(uint32_t dst, const float* src) {
    size_t s = __cvta_generic_to_global(src);
    asm volatile("cp.async.cg.shared.global [%0], [%1], 16;" :: "r"(dst), "l"(s) : "memory");
}
__device__ __forceinline__ uint32_t smem_u32(const void* p) {
    uint32_t a;
    asm("{ .reg .u64 t; cvta.to.shared.u64 t, %1; cvt.u32.u64 %0, t; }" : "=r"(a) : "l"(p));
    return a;
}
__device__ __forceinline__ void ldsm_x4(uint32_t a[4], uint32_t addr) {
    asm volatile("ldmatrix.sync.aligned.m8n8.x4.shared.b16 {%0,%1,%2,%3}, [%4];"
                 : "=r"(a[0]), "=r"(a[1]), "=r"(a[2]), "=r"(a[3]) : "r"(addr));
}
__device__ __forceinline__ void ldsm_x2(uint32_t b[2], uint32_t addr) {
    asm volatile("ldmatrix.sync.aligned.m8n8.x2.shared.b16 {%0,%1}, [%2];"
                 : "=r"(b[0]), "=r"(b[1]) : "r"(addr));
}
__device__ __forceinline__ void mma16816(float c[4], const uint32_t a[4], const uint32_t b[2]) {
    asm volatile(
        "mma.sync.aligned.m16n8k16.row.col.f32.bf16.bf16.f32 "
        "{%0,%1,%2,%3}, {%4,%5,%6,%7}, {%8,%9}, {%0,%1,%2,%3};"
        : "+f"(c[0]), "+f"(c[1]), "+f"(c[2]), "+f"(c[3])
        : "r"(a[0]), "r"(a[1]), "r"(a[2]), "r"(a[3]), "r"(b[0]), "r"(b[1]));
}

__global__ void __launch_bounds__(256, 1) gru_fused_kernel(
        const float* __restrict__ x,
        const float* __restrict__ W_ih,
        const float* __restrict__ W_hh,
        const float* __restrict__ b_ih,
        const float* __restrict__ b_hh,
        const float* __restrict__ w_head,
        const float* __restrict__ b_head,
        float* __restrict__ out) {
    extern __shared__ __align__(128) char sm[];

    const int tid = threadIdx.x;
    const int w = tid >> 5;
    const int lane = tid & 31;
    const int gw = blockIdx.x * WPB + w;     // warp owns batch rows 4gw..4gw+3

    // ── CTA init: W_ih → smem bf16 hi/lo (80B row stride), bias ──
    for (int i = tid; i < 96 * 32; i += 256) {
        int r = i >> 5, c = i & 31;
        float v = W_ih[i];
        __nv_bfloat16 hi = __float2bfloat16(v);
        __nv_bfloat16 lo = __float2bfloat16(v - __bfloat162float(hi));
        *(__nv_bfloat16*)(sm + S_WHI + r * 80 + c * 2) = hi;
        *(__nv_bfloat16*)(sm + S_WLO + r * 80 + c * 2) = lo;
    }
    if (tid < 96)
        *(float*)(sm + S_BIAS + tid * 4) = b_ih[tid] + (tid < 64 ? b_hh[tid] : 0.0f);

    // ── W_hh rows lane, 32+lane, 64+lane packed into registers ──
    u64 whr[16], whz[16], whn[16];
    {
        const u64* a = (const u64*)(W_hh + (size_t)lane * 32);
        const u64* c = (const u64*)(W_hh + (size_t)(32 + lane) * 32);
        const u64* d = (const u64*)(W_hh + (size_t)(64 + lane) * 32);
#pragma unroll
        for (int k = 0; k < 16; k++) { whr[k] = a[k]; whz[k] = c[k]; whn[k] = d[k]; }
    }
    const u64 anh0 = pack2(b_hh[64 + lane], 0.0f);
    const u64 zero2 = pack2(0.0f, 0.0f);
    __syncthreads();

    // ── per-warp smem addresses ──
    const uint32_t smb = smem_u32(sm);
    const uint32_t xsb = smb + S_XS + w * 8192;       // fp32 x staging (2×4096B)
    const uint32_t xth = smb + S_XT + w * 5120;       // bf16 x hi (32 rows × 80B)
    const uint32_t xtl = xth + 2560;                  // bf16 x lo
    float* gxs = (float*)(sm + S_GX + w * 12288);     // gx chunk: 4 rows × 8 × 96
    float* hb  = (float*)(sm + S_HB + w * 1024);      // [buf][row][32]
    const float* biasf = (const float*)(sm + S_BIAS);

    const float* xr[RPW];
#pragma unroll
    for (int r = 0; r < RPW; r++) xr[r] = x + (size_t)(RPW * gw + r) * GRU_T * 32;

    // frag addressing constants
    const int gq = lane >> 3;
    const uint32_t a_roff = (uint32_t)(((gq & 1) * 8 + (lane & 7)) * 80 + (gq >> 1) * 16);
    const int mh = lane & 15;
    const uint32_t w_roff = (uint32_t)((mh & 7) * 80 + ((mh >> 3) & 1) * 16);

    // ── x staging: 4KB per chunk per warp (4 rows × 1KB), step-swizzled ──
    auto stage_x = [&](int cc) {
        uint32_t dst = xsb + (cc & 1) * 4096;
#pragma unroll
        for (int r = 0; r < RPW; r++) {
            const float* s = xr[r] + (size_t)cc * CHUNK * 32;
#pragma unroll
            for (int i = 0; i < 2; i++) {
                int stp = i * 4 + (lane >> 3);
                uint32_t phys = (uint32_t)(r * 1024 + stp * 128 + (((lane & 7) ^ stp) << 4));
                cpasync16(dst + phys, s + i * 128 + lane * 4);
            }
        }
    };
    stage_x(0);
    asm volatile("cp.async.commit_group;" ::: "memory");
    stage_x(1);
    asm volatile("cp.async.commit_group;" ::: "memory");

    float h[RPW];
#pragma unroll
    for (int r = 0; r < RPW; r++) { h[r] = 0.0f; hb[r * 32 + lane] = 0.0f; }
    __syncwarp();

#pragma unroll 1
    for (int c = 0; c < NCH; c++) {
        // ── produce gx chunk c (tensor pipe) ──
        asm volatile("cp.async.wait_group 1;" ::: "memory");
        __syncwarp();

        // fp32 x → hi/lo bf16 tiles. Lane = m-row (0..31).
        {
            const int tile = lane >> 4;
            const int lm = lane & 15;
            const int rr = tile * 2 + (lm >> 3);     // batch row in warp
            const int stp = lm & 7;
            const char* sbase = sm + (S_XS + w * 8192) + (c & 1) * 4096
                              + rr * 1024 + stp * 128;
            uint32_t hu[16], lu[16];
#pragma unroll
            for (int q = 0; q < 8; q++) {
                float4 v = *(const float4*)(sbase + ((q ^ stp) << 4));
                __nv_bfloat162 hA = __floats2bfloat162_rn(v.x, v.y);
                __nv_bfloat162 hB = __floats2bfloat162_rn(v.z, v.w);
                __nv_bfloat162 lA = __floats2bfloat162_rn(v.x - __bfloat162float(hA.x),
                                                          v.y - __bfloat162float(hA.y));
                __nv_bfloat162 lB = __floats2bfloat162_rn(v.z - __bfloat162float(hB.x),
                                                          v.w - __bfloat162float(hB.y));
                hu[2 * q]     = *(uint32_t*)&hA;
                hu[2 * q + 1] = *(uint32_t*)&hB;
                lu[2 * q]     = *(uint32_t*)&lA;
                lu[2 * q + 1] = *(uint32_t*)&lB;
            }
            uint4* dh = (uint4*)(sm + (xth - smb) + lane * 80);
            uint4* dl = (uint4*)(sm + (xtl - smb) + lane * 80);
#pragma unroll
            for (int q = 0; q < 4; q++) {
                dh[q] = make_uint4(hu[4 * q], hu[4 * q + 1], hu[4 * q + 2], hu[4 * q + 3]);
                dl[q] = make_uint4(lu[4 * q], lu[4 * q + 1], lu[4 * q + 2], lu[4 * q + 3]);
            }
        }
        __syncwarp();

        // A fragments: 2 m16 tiles (rows 0-1, rows 2-3) × hi/lo × 2 k-steps.
        uint32_t ah[2][2][4], al[2][2][4];
#pragma unroll
        for (int tt = 0; tt < 2; tt++)
#pragma unroll
            for (int ks = 0; ks < 2; ks++) {
                ldsm_x4(ah[tt][ks], xth + tt * 1280 + a_roff + ks * 32);
                ldsm_x4(al[tt][ks], xtl + tt * 1280 + a_roff + ks * 32);
            }

        // prefetch x for chunk c+2 (buf c&1 reads are done)
        if (c + 2 < NCH) stage_x(c + 2);
        asm volatile("cp.async.commit_group;" ::: "memory");

        // 12 n-tiles; B frags shared across both A tiles; C init = bias.
#pragma unroll
        for (int nt = 0; nt < 12; nt++) {
            uint32_t bh0[2], bh1[2], bl0[2], bl1[2];
            ldsm_x2(bh0, smb + S_WHI + nt * 640 + w_roff);
            ldsm_x2(bh1, smb + S_WHI + nt * 640 + w_roff + 32);
            ldsm_x2(bl0, smb + S_WLO + nt * 640 + w_roff);
            ldsm_x2(bl1, smb + S_WLO + nt * 640 + w_roff + 32);
            float2 b2 = *(const float2*)(biasf + nt * 8 + (lane & 3) * 2);
#pragma unroll
            for (int tt = 0; tt < 2; tt++) {
                float cc4[4] = { b2.x, b2.y, b2.x, b2.y };
                mma16816(cc4, ah[tt][0], bh0);
                mma16816(cc4, ah[tt][1], bh1);
                mma16816(cc4, ah[tt][0], bl0);
                mma16816(cc4, ah[tt][1], bl1);
                mma16816(cc4, al[tt][0], bh0);
                mma16816(cc4, al[tt][1], bh1);
                float* o = gxs + tt * 1536 + (lane >> 2) * 96 + nt * 8 + (lane & 3) * 2;
                *(float2*)o         = make_float2(cc4[0], cc4[1]);
                *(float2*)(o + 768) = make_float2(cc4[2], cc4[3]);
            }
        }
        __syncwarp();

        // ── consume: 8 recurrence steps (fma pipe) ──
#pragma unroll 2
        for (int tl = 0; tl < CHUNK; tl++) {
            const int t = c * CHUNK + tl;
            u64 ar[RPW], az[RPW], an[RPW];
#pragma unroll
            for (int r = 0; r < RPW; r++) { ar[r] = zero2; az[r] = zero2; an[r] = anh0; }

#pragma unroll
            for (int q = 0; q < 8; q++) {
#pragma unroll
                for (int r = 0; r < RPW; r++) {
                    ulonglong2 hh = ((const ulonglong2*)(hb + (t & 1) * 128 + r * 32))[q];
                    ar[r] = ffma2(hh.x, whr[2 * q], ar[r]);
                    az[r] = ffma2(hh.x, whz[2 * q], az[r]);
                    an[r] = ffma2(hh.x, whn[2 * q], an[r]);
                    ar[r] = ffma2(hh.y, whr[2 * q + 1], ar[r]);
                    az[r] = ffma2(hh.y, whz[2 * q + 1], az[r]);
                    an[r] = ffma2(hh.y, whn[2 * q + 1], an[r]);
                }
            }
#pragma unroll
            for (int r = 0; r < RPW; r++) {
                float gxr = gxs[r * 768 + tl * 96 + lane];
                float gxz = gxs[r * 768 + tl * 96 + 32 + lane];
                float gxn = gxs[r * 768 + tl * 96 + 64 + lane];
                float2 fr = unpack2(ar[r]), fz = unpack2(az[r]), fn = unpack2(an[r]);
                float rr = sigmoid_fast(gxr + fr.x + fr.y);
                float zz = sigmoid_fast(gxz + fz.x + fz.y);
                float nn = tanh_fast(fmaf(rr, fn.x + fn.y, gxn));
                h[r] = fmaf(zz, h[r] - nn, nn);
                hb[((t + 1) & 1) * 128 + r * 32 + lane] = h[r];
            }
            __syncwarp();
        }
    }

    // ── head ──
    float v[RPW];
#pragma unroll
    for (int r = 0; r < RPW; r++) v[r] = h[r] * w_head[lane];
#pragma unroll
    for (int off = 16; off > 0; off >>= 1)
#pragma unroll
        for (int r = 0; r < RPW; r++) v[r] += __shfl_xor_sync(FULL, v[r], off);
    if (lane == 0) {
#pragma unroll
        for (int r = 0; r < RPW; r++) out[RPW * gw + r] = v[r] + b_head[0];
    }
}

extern "C" void kernel_launch(void* const* d_in, const int* in_sizes, int n_in,
                              void* d_out, int out_size) {
    const float* x      = (const float*)d_in[0];
    const float* W_ih   = (const float*)d_in[1];
    const float* W_hh   = (const float*)d_in[2];
    const float* b_ih   = (const float*)d_in[3];
    const float* b_hh   = (const float*)d_in[4];
    const float* w_head = (const float*)d_in[5];
    const float* b_head = (const float*)d_in[6];
    float* out = (float*)d_out;

    cudaFuncSetAttribute(gru_fused_kernel,
                         cudaFuncAttributeMaxDynamicSharedMemorySize, S_TOTAL);
    gru_fused_kernel<<<GRID, 32 * WPB, S_TOTAL>>>(
        x, W_ih, W_hh, b_ih, b_hh, w_head, b_head, out);
}

// round 17
// speedup vs baseline: 1.4399x; 1.4095x over previous
#include <cuda_runtime.h>
#include <cuda_bf16.h>
#include <cstdint>

// GRU B=4096, T=512, I=H=32 — tensor-core recurrence.
// CTA = 4 warps = 16 batch rows (one m16 tile), 256 CTAs, 2 CTAs/SM.
// Per step: h (bf16 hi/lo in smem) -> ldmatrix A-frags; warp k holds W_hh
// B-frags for n-tiles {k,4+k,8+k}; 18 mma (3-term split) give gh_r/z/n in frag
// layout; gates + h-update elementwise in frags; h hi/lo STS for next step.
// x-side gx produced per 4-step chunk with the proven mma pipeline into smem.

#define GRU_T 512
#define GRU_B 4096
#define CHUNK 4
#define NCH (GRU_T / CHUNK)       // 128
#define GRID (GRU_B / 16)         // 256
#define FULL 0xffffffffu

// ── smem layout (bytes) ──
#define S_WIHH 0                  // W_ih hi bf16: 96 x 80B
#define S_WIHL 7680               // W_ih lo
#define S_WHHH 15360              // W_hh hi
#define S_WHHL 23040              // W_hh lo
#define S_BIAS 30720              // 96 f32 (b_ih + b_hh folded for r,z)
#define S_XS   31104              // x fp32 staging: 2 buf x 8192B
#define S_XT   47488              // x bf16 tiles: hi 5120 + lo 5120
#define S_GX   57728              // gx: 64 m-rows x 400B (100 f32 stride)
#define S_HT   83328              // h tiles: 2 buf x (hi 1280 + lo 1280)
#define S_TOTAL 88448

#define GXSTR 100                 // gx row stride in floats (bank-spread)

__device__ __forceinline__ float sigmoid_fast(float v) {
    float e = __expf(-v);
    return __fdividef(1.0f, 1.0f + e);
}
__device__ __forceinline__ float tanh_fast(float v) {
    float a = fabsf(v);
    float e = __expf(-2.0f * a);
    float t = __fdividef(1.0f - e, 1.0f + e);
    return copysignf(t, v);
}
__device__ __forceinline__ void cpasync16(uint32_t dst, const float* src) {
    size_t s = __cvta_generic_to_global(src);
    asm volatile("cp.async.cg.shared.global [%0], [%1], 16;" :: "r"(dst), "l"(s) : "memory");
}
__device__ __forceinline__ uint32_t smem_u32(const void* p) {
    uint32_t a;
    asm("{ .reg .u64 t; cvta.to.shared.u64 t, %1; cvt.u32.u64 %0, t; }" : "=r"(a) : "l"(p));
    return a;
}
__device__ __forceinline__ void ldsm_x4(uint32_t a[4], uint32_t addr) {
    asm volatile("ldmatrix.sync.aligned.m8n8.x4.shared.b16 {%0,%1,%2,%3}, [%4];"
                 : "=r"(a[0]), "=r"(a[1]), "=r"(a[2]), "=r"(a[3]) : "r"(addr));
}
__device__ __forceinline__ void ldsm_x2(uint32_t b[2], uint32_t addr) {
    asm volatile("ldmatrix.sync.aligned.m8n8.x2.shared.b16 {%0,%1}, [%2];"
                 : "=r"(b[0]), "=r"(b[1]) : "r"(addr));
}
__device__ __forceinline__ void mma16816(float c[4], const uint32_t a[4], const uint32_t b[2]) {
    asm volatile(
        "mma.sync.aligned.m16n8k16.row.col.f32.bf16.bf16.f32 "
        "{%0,%1,%2,%3}, {%4,%5,%6,%7}, {%8,%9}, {%0,%1,%2,%3};"
        : "+f"(c[0]), "+f"(c[1]), "+f"(c[2]), "+f"(c[3])
        : "r"(a[0]), "r"(a[1]), "r"(a[2]), "r"(a[3]), "r"(b[0]), "r"(b[1]));
}

__global__ void __launch_bounds__(128, 2) gru_tensor_kernel(
        const float* __restrict__ x,
        const float* __restrict__ W_ih,
        const float* __restrict__ W_hh,
        const float* __restrict__ b_ih,
        const float* __restrict__ b_hh,
        const float* __restrict__ w_head,
        const float* __restrict__ b_head,
        float* __restrict__ out) {
    extern __shared__ __align__(128) char sm[];
    const uint32_t smb = smem_u32(sm);
    const int tid = threadIdx.x;
    const int w = tid >> 5;          // warp 0..3: owns n-tiles {w, 4+w, 8+w}
    const int lane = tid & 31;
    const size_t row0g = (size_t)blockIdx.x * 16;   // CTA's 16 batch rows

    // ── init: weights -> smem bf16 hi/lo (80B stride), bias ──
    for (int i = tid; i < 96 * 32; i += 128) {
        int r = i >> 5, c = i & 31;
        float vi = W_ih[i], vh = W_hh[i];
        __nv_bfloat16 ih = __float2bfloat16(vi);
        __nv_bfloat16 il = __float2bfloat16(vi - __bfloat162float(ih));
        __nv_bfloat16 hh = __float2bfloat16(vh);
        __nv_bfloat16 hl = __float2bfloat16(vh - __bfloat162float(hh));
        *(__nv_bfloat16*)(sm + S_WIHH + r * 80 + c * 2) = ih;
        *(__nv_bfloat16*)(sm + S_WIHL + r * 80 + c * 2) = il;
        *(__nv_bfloat16*)(sm + S_WHHH + r * 80 + c * 2) = hh;
        *(__nv_bfloat16*)(sm + S_WHHL + r * 80 + c * 2) = hl;
    }
    if (tid < 96)
        *(float*)(sm + S_BIAS + tid * 4) = b_ih[tid] + (tid < 64 ? b_hh[tid] : 0.0f);
    // zero h tile buf 0 (both planes)
    for (int i = tid; i < 640; i += 128) ((uint32_t*)(sm + S_HT))[i] = 0;
    __syncthreads();

    // ── W_hh B-frags for this warp's 3 n-tiles (registers, permanent) ──
    const int mh = lane & 15;
    const uint32_t w_roff = (uint32_t)((mh & 7) * 80 + ((mh >> 3) & 1) * 16);
    uint32_t Bh[3][2][2], Bl[3][2][2];
#pragma unroll
    for (int i = 0; i < 3; i++) {
        int nt = w + 4 * i;
#pragma unroll
        for (int ks = 0; ks < 2; ks++) {
            ldsm_x2(Bh[i][ks], smb + S_WHHH + nt * 640 + w_roff + ks * 32);
            ldsm_x2(Bl[i][ks], smb + S_WHHL + nt * 640 + w_roff + ks * 32);
        }
    }
    // n-gate hidden bias for this lane's 2 cols (j0 = 8w + (lane&3)*2)
    const int j0 = 8 * w + (lane & 3) * 2;
    const float2 bnh = *(const float2*)(b_hh + 64 + j0);

    // frag addressing
    const int gq = lane >> 3;
    const uint32_t a_roff = (uint32_t)(((gq & 1) * 8 + (lane & 7)) * 80 + (gq >> 1) * 16);
    const int r0 = lane >> 2;         // frag row 0 (0..7); row1 = r0+8
    const int r1 = r0 + 8;

    // ── x staging: thread stages exactly what it later converts ──
    // m = t_local*16 + row  (m 0..63); thread: m = tid>>1, half = tid&1.
    const int sm_m = tid >> 1;
    const int sm_half = tid & 1;
    const float* xrow = x + (row0g + (sm_m & 15)) * (GRU_T * 32);
    const int sm_t = sm_m >> 4;
    auto stage_x = [&](int cc) {
        uint32_t dst = smb + S_XS + (cc & 1) * 8192;
        const float* src = xrow + (size_t)(cc * CHUNK + sm_t) * 32;
#pragma unroll
        for (int q = 0; q < 4; q++) {
            int c16 = sm_half * 4 + q;
            uint32_t phys = (uint32_t)(sm_m * 128 + ((c16 ^ (sm_m & 7)) << 4));
            cpasync16(dst + phys, src + c16 * 4);
        }
    };
    stage_x(0);
    asm volatile("cp.async.commit_group;" ::: "memory");
    stage_x(1);
    asm volatile("cp.async.commit_group;" ::: "memory");

    float h[4] = {0.0f, 0.0f, 0.0f, 0.0f};   // (r0,j0),(r0,j0+1),(r1,j0),(r1,j0+1)

#pragma unroll 1
    for (int cc = 0; cc < NCH; cc++) {
        // 1. own staged data ready
        asm volatile("cp.async.wait_group 1;" ::: "memory");

        // 2. cvt x fp32 -> bf16 hi/lo tiles (thread reads its own staged rows)
        {
            const char* sbase = sm + S_XS + (cc & 1) * 8192 + sm_m * 128;
            uint32_t hu[8], lu[8];
#pragma unroll
            for (int q = 0; q < 4; q++) {
                int c16 = sm_half * 4 + q;
                float4 v = *(const float4*)(sbase + ((c16 ^ (sm_m & 7)) << 4));
                __nv_bfloat162 hA = __floats2bfloat162_rn(v.x, v.y);
                __nv_bfloat162 hB = __floats2bfloat162_rn(v.z, v.w);
                __nv_bfloat162 lA = __floats2bfloat162_rn(v.x - __bfloat162float(hA.x),
                                                          v.y - __bfloat162float(hA.y));
                __nv_bfloat162 lB = __floats2bfloat162_rn(v.z - __bfloat162float(hB.x),
                                                          v.w - __bfloat162float(hB.y));
                hu[2 * q] = *(uint32_t*)&hA; hu[2 * q + 1] = *(uint32_t*)&hB;
                lu[2 * q] = *(uint32_t*)&lA; lu[2 * q + 1] = *(uint32_t*)&lB;
            }
            uint4* dh = (uint4*)(sm + S_XT + sm_m * 80 + sm_half * 32);
            uint4* dl = (uint4*)(sm + S_XT + 5120 + sm_m * 80 + sm_half * 32);
            dh[0] = make_uint4(hu[0], hu[1], hu[2], hu[3]);
            dh[1] = make_uint4(hu[4], hu[5], hu[6], hu[7]);
            dl[0] = make_uint4(lu[0], lu[1], lu[2], lu[3]);
            dl[1] = make_uint4(lu[4], lu[5], lu[6], lu[7]);
        }
        __syncthreads();

        // 3. produce gx for this chunk: warp w = chunk-step w (m-tile w)
        {
            uint32_t ah[2][4], al[2][4];
#pragma unroll
            for (int ks = 0; ks < 2; ks++) {
                ldsm_x4(ah[ks], smb + S_XT + w * 1280 + a_roff + ks * 32);
                ldsm_x4(al[ks], smb + S_XT + 5120 + w * 1280 + a_roff + ks * 32);
            }
#pragma unroll
            for (int nt = 0; nt < 12; nt++) {
                uint32_t bh0[2], bh1[2], bl0[2], bl1[2];
                ldsm_x2(bh0, smb + S_WIHH + nt * 640 + w_roff);
                ldsm_x2(bh1, smb + S_WIHH + nt * 640 + w_roff + 32);
                ldsm_x2(bl0, smb + S_WIHL + nt * 640 + w_roff);
                ldsm_x2(bl1, smb + S_WIHL + nt * 640 + w_roff + 32);
                float2 b2 = *(const float2*)(sm + S_BIAS + (nt * 8 + (lane & 3) * 2) * 4);
                float c4[4] = { b2.x, b2.y, b2.x, b2.y };
                mma16816(c4, ah[0], bh0);
                mma16816(c4, ah[1], bh1);
                mma16816(c4, ah[0], bl0);
                mma16816(c4, ah[1], bl1);
                mma16816(c4, al[0], bh0);
                mma16816(c4, al[1], bh1);
                int m0 = w * 16 + r0, m1 = w * 16 + r1;
                float* o0 = (float*)(sm + S_GX) + m0 * GXSTR + nt * 8 + (lane & 3) * 2;
                float* o1 = (float*)(sm + S_GX) + m1 * GXSTR + nt * 8 + (lane & 3) * 2;
                *(float2*)o0 = make_float2(c4[0], c4[1]);
                *(float2*)o1 = make_float2(c4[2], c4[3]);
            }
        }
        __syncthreads();

        // 4. prefetch chunk cc+2 (its reads finished before last sync)
        if (cc + 2 < NCH) stage_x(cc + 2);
        asm volatile("cp.async.commit_group;" ::: "memory");

        // 5. consume: 4 recurrence steps, all in frag layout
#pragma unroll
        for (int tl = 0; tl < CHUNK; tl++) {
            const int t = cc * CHUNK + tl;
            const uint32_t hbase = smb + S_HT + (t & 1) * 2560;

            uint32_t ah2[2][4], al2[2][4];
#pragma unroll
            for (int ks = 0; ks < 2; ks++) {
                ldsm_x4(ah2[ks], hbase + a_roff + ks * 32);
                ldsm_x4(al2[ks], hbase + 1280 + a_roff + ks * 32);
            }

            const float* gx0 = (const float*)(sm + S_GX) + (tl * 16 + r0) * GXSTR;
            const float* gx1 = (const float*)(sm + S_GX) + (tl * 16 + r1) * GXSTR;
            float2 gr0 = *(const float2*)(gx0 + j0);
            float2 gr1 = *(const float2*)(gx1 + j0);
            float2 gz0 = *(const float2*)(gx0 + 32 + j0);
            float2 gz1 = *(const float2*)(gx1 + 32 + j0);
            float cr[4] = { gr0.x, gr0.y, gr1.x, gr1.y };
            float cz[4] = { gz0.x, gz0.y, gz1.x, gz1.y };
            float cn[4] = { bnh.x, bnh.y, bnh.x, bnh.y };

#pragma unroll
            for (int i = 0; i < 3; i++) {
                float* c4 = (i == 0) ? cr : (i == 1) ? cz : cn;
                mma16816(c4, ah2[0], Bh[i][0]);
                mma16816(c4, ah2[1], Bh[i][1]);
                mma16816(c4, ah2[0], Bl[i][0]);
                mma16816(c4, ah2[1], Bl[i][1]);
                mma16816(c4, al2[0], Bh[i][0]);
                mma16816(c4, al2[1], Bh[i][1]);
            }

            float2 gn0 = *(const float2*)(gx0 + 64 + j0);
            float2 gn1 = *(const float2*)(gx1 + 64 + j0);
            float gxn[4] = { gn0.x, gn0.y, gn1.x, gn1.y };
#pragma unroll
            for (int e = 0; e < 4; e++) {
                float rr = sigmoid_fast(cr[e]);
                float zz = sigmoid_fast(cz[e]);
                float nn = tanh_fast(fmaf(rr, cn[e], gxn[e]));
                h[e] = fmaf(zz, h[e] - nn, nn);
            }

            // h -> bf16 hi/lo, STS into buf (t+1)&1
            __nv_bfloat162 h01 = __floats2bfloat162_rn(h[0], h[1]);
            __nv_bfloat162 h23 = __floats2bfloat162_rn(h[2], h[3]);
            __nv_bfloat162 l01 = __floats2bfloat162_rn(h[0] - __bfloat162float(h01.x),
                                                       h[1] - __bfloat162float(h01.y));
            __nv_bfloat162 l23 = __floats2bfloat162_rn(h[2] - __bfloat162float(h23.x),
                                                       h[3] - __bfloat162float(h23.y));
            char* nb = sm + S_HT + ((t + 1) & 1) * 2560;
            *(uint32_t*)(nb + r0 * 80 + j0 * 2) = *(uint32_t*)&h01;
            *(uint32_t*)(nb + r1 * 80 + j0 * 2) = *(uint32_t*)&h23;
            *(uint32_t*)(nb + 1280 + r0 * 80 + j0 * 2) = *(uint32_t*)&l01;
            *(uint32_t*)(nb + 1280 + r1 * 80 + j0 * 2) = *(uint32_t*)&l23;
            __syncthreads();
        }
    }

    // ── head: collect h (fp32) in smem, per-warp row reductions ──
    {
        float* hfin = (float*)(sm + S_GX);
        *(float2*)(hfin + r0 * 32 + j0) = make_float2(h[0], h[1]);
        *(float2*)(hfin + r1 * 32 + j0) = make_float2(h[2], h[3]);
        __syncthreads();
        const float wh = w_head[lane];
#pragma unroll
        for (int rr = 0; rr < 4; rr++) {
            int row = w * 4 + rr;
            float v = hfin[row * 32 + lane] * wh;
#pragma unroll
            for (int off = 16; off > 0; off >>= 1)
                v += __shfl_xor_sync(FULL, v, off);
            if (lane == 0) out[row0g + row] = v + b_head[0];
        }
    }
}

extern "C" void kernel_launch(void* const* d_in, const int* in_sizes, int n_in,
                              void* d_out, int out_size) {
    const float* x      = (const float*)d_in[0];
    const float* W_ih   = (const float*)d_in[1];
    const float* W_hh   = (const float*)d_in[2];
    const float* b_ih   = (const float*)d_in[3];
    const float* b_hh   = (const float*)d_in[4];
    const float* w_head = (const float*)d_in[5];
    const float* b_head = (const float*)d_in[6];
    float* out = (float*)d_out;

    cudaFuncSetAttribute(gru_tensor_kernel,
                         cudaFuncAttributeMaxDynamicSharedMemorySize, S_TOTAL);
    gru_tensor_kernel<<<GRID, 128, S_TOTAL>>>(
        x, W_ih, W_hh, b_ih, b_hh, w_head, b_head, out);
}